// round 3
// baseline (speedup 1.0000x reference)
#include <cuda_runtime.h>
#include <cstdint>

#define B_   2
#define N_   8192
#define FIN_ 128
#define FO_  64

// tf32-pre-rounded q,k,v (bit patterns), 12.6 MB device scratch
__device__ __align__(16) uint32_t g_qkv[3][(size_t)B_ * N_ * FO_];

__device__ __forceinline__ uint32_t f2tf(float x) {
    uint32_t r;
    asm("cvt.rna.tf32.f32 %0, %1;" : "=r"(r) : "f"(x));
    return r;
}

__device__ __forceinline__ void mma8(float c[4], const uint32_t a[4],
                                     uint32_t b0, uint32_t b1) {
    asm volatile(
        "mma.sync.aligned.m16n8k8.row.col.f32.tf32.tf32.f32 "
        "{%0,%1,%2,%3}, {%4,%5,%6,%7}, {%8,%9}, {%0,%1,%2,%3};\n"
        : "+f"(c[0]), "+f"(c[1]), "+f"(c[2]), "+f"(c[3])
        : "r"(a[0]), "r"(a[1]), "r"(a[2]), "r"(a[3]), "r"(b0), "r"(b1));
}

// ---------------------------------------------------------------------------
// Kernel 1: fused 2-layer MLP (q/k/v selected by blockIdx.y), 64 rows/block
// ---------------------------------------------------------------------------
#define LX 136   // feature tile row stride (floats)
#define LW 72    // weight / hidden tile row stride (floats)

__global__ void __launch_bounds__(128)
mlp_kernel(const float* __restrict__ feature,
           const float* __restrict__ Wa0, const float* __restrict__ ba0,
           const float* __restrict__ Wb0, const float* __restrict__ bb0,
           const float* __restrict__ Wa1, const float* __restrict__ ba1,
           const float* __restrict__ Wb1, const float* __restrict__ bb1,
           const float* __restrict__ Wa2, const float* __restrict__ ba2,
           const float* __restrict__ Wb2, const float* __restrict__ bb2)
{
    extern __shared__ uint32_t sm_[];
    uint32_t* Xs  = sm_;                  // 64 x LX
    uint32_t* W1s = Xs + 64 * LX;         // 128 x LW
    uint32_t* W2s = W1s + 128 * LW;       // 64 x LW
    uint32_t* Hs  = W2s + 64 * LW;        // 64 x LW

    const int which = blockIdx.y;
    const float* Wa = which == 0 ? Wa0 : which == 1 ? Wa1 : Wa2;
    const float* ba = which == 0 ? ba0 : which == 1 ? ba1 : ba2;
    const float* Wb = which == 0 ? Wb0 : which == 1 ? Wb1 : Wb2;
    const float* bb = which == 0 ? bb0 : which == 1 ? bb1 : bb2;

    const int tid  = threadIdx.x;
    const int row0 = blockIdx.x * 64;

    // load feature tile (64 x 128, contiguous rows) with tf32 rounding
    {
        const float4* f4 = (const float4*)(feature + (size_t)row0 * FIN_);
        for (int i = tid; i < 64 * (FIN_ / 4); i += 128) {
            float4 v = f4[i];
            uint32_t* d = Xs + (i >> 5) * LX + ((i & 31) << 2);
            d[0] = f2tf(v.x); d[1] = f2tf(v.y); d[2] = f2tf(v.z); d[3] = f2tf(v.w);
        }
        const float4* w4 = (const float4*)Wa;     // 128 x 64
        for (int i = tid; i < FIN_ * (FO_ / 4); i += 128) {
            float4 v = w4[i];
            uint32_t* d = W1s + (i >> 4) * LW + ((i & 15) << 2);
            d[0] = f2tf(v.x); d[1] = f2tf(v.y); d[2] = f2tf(v.z); d[3] = f2tf(v.w);
        }
        const float4* w24 = (const float4*)Wb;    // 64 x 64
        for (int i = tid; i < FO_ * (FO_ / 4); i += 128) {
            float4 v = w24[i];
            uint32_t* d = W2s + (i >> 4) * LW + ((i & 15) << 2);
            d[0] = f2tf(v.x); d[1] = f2tf(v.y); d[2] = f2tf(v.z); d[3] = f2tf(v.w);
        }
    }
    __syncthreads();

    const int lane = tid & 31, warp = tid >> 5;
    const int gid = lane >> 2, tig = lane & 3;
    const int rw = warp * 16;

    float C[8][4];
#pragma unroll
    for (int nt = 0; nt < 8; nt++) { C[nt][0] = C[nt][1] = C[nt][2] = C[nt][3] = 0.f; }

    // layer 1: [64x128] @ [128x64]
#pragma unroll
    for (int kc = 0; kc < 16; kc++) {
        uint32_t a[4];
        const uint32_t* Ar = Xs + (rw + gid) * LX + kc * 8 + tig;
        a[0] = Ar[0]; a[2] = Ar[4]; a[1] = Ar[8 * LX]; a[3] = Ar[8 * LX + 4];
#pragma unroll
        for (int nt = 0; nt < 8; nt++) {
            const uint32_t* Br = W1s + (kc * 8 + tig) * LW + nt * 8 + gid;
            mma8(C[nt], a, Br[0], Br[4 * LW]);
        }
    }
    // bias + relu -> Hs (tf32)
#pragma unroll
    for (int nt = 0; nt < 8; nt++) {
        int col = nt * 8 + 2 * tig;
        float bx = ba[col], by = ba[col + 1];
        Hs[(rw + gid) * LW + col]         = f2tf(fmaxf(C[nt][0] + bx, 0.f));
        Hs[(rw + gid) * LW + col + 1]     = f2tf(fmaxf(C[nt][1] + by, 0.f));
        Hs[(rw + gid + 8) * LW + col]     = f2tf(fmaxf(C[nt][2] + bx, 0.f));
        Hs[(rw + gid + 8) * LW + col + 1] = f2tf(fmaxf(C[nt][3] + by, 0.f));
    }
    __syncwarp();   // Hs rows are warp-private

    // layer 2: [64x64] @ [64x64]
#pragma unroll
    for (int nt = 0; nt < 8; nt++) { C[nt][0] = C[nt][1] = C[nt][2] = C[nt][3] = 0.f; }
#pragma unroll
    for (int kc = 0; kc < 8; kc++) {
        uint32_t a[4];
        const uint32_t* Ar = Hs + (rw + gid) * LW + kc * 8 + tig;
        a[0] = Ar[0]; a[2] = Ar[4]; a[1] = Ar[8 * LW]; a[3] = Ar[8 * LW + 4];
#pragma unroll
        for (int nt = 0; nt < 8; nt++) {
            const uint32_t* Br = W2s + (kc * 8 + tig) * LW + nt * 8 + gid;
            mma8(C[nt], a, Br[0], Br[4 * LW]);
        }
    }
    uint32_t* outp = g_qkv[which];
#pragma unroll
    for (int nt = 0; nt < 8; nt++) {
        int col = nt * 8 + 2 * tig;
        float bx = bb[col], by = bb[col + 1];
        uint2 o0 = make_uint2(f2tf(fmaxf(C[nt][0] + bx, 0.f)),
                              f2tf(fmaxf(C[nt][1] + by, 0.f)));
        uint2 o1 = make_uint2(f2tf(fmaxf(C[nt][2] + bx, 0.f)),
                              f2tf(fmaxf(C[nt][3] + by, 0.f)));
        *(uint2*)(outp + (size_t)(row0 + rw + gid) * FO_ + col)     = o0;
        *(uint2*)(outp + (size_t)(row0 + rw + gid + 8) * FO_ + col) = o1;
    }
}

// ---------------------------------------------------------------------------
// Kernel 2: flash attention with x_weight, BM=128, BN=64, 8 warps
// ---------------------------------------------------------------------------
#define LS 72
#define BM 128
#define BN 64

__global__ void __launch_bounds__(256)
attn_kernel(const float* __restrict__ xw, float* __restrict__ out)
{
    extern __shared__ uint32_t sm_[];
    uint32_t* Ks = sm_;                       // BN x LS (tf32)
    uint32_t* Vs = Ks + BN * LS;              // BN x LS (tf32)
    float*    Wsh = (float*)(Vs + BN * LS);   // BM x LS (fp32)
    uint32_t* Ps = (uint32_t*)Wsh + BM * LS;  // BM x LS (tf32)

    const int b  = blockIdx.y;
    const int q0 = blockIdx.x * BM;
    const int tid = threadIdx.x, lane = tid & 31, warp = tid >> 5;
    const int gid = lane >> 2, tig = lane & 3;
    const int rw = warp * 16;

    const uint32_t* qb = g_qkv[0] + (size_t)b * N_ * FO_;
    const uint32_t* kb = g_qkv[1] + (size_t)b * N_ * FO_;
    const uint32_t* vb = g_qkv[2] + (size_t)b * N_ * FO_;
    const float*    wb = xw + (size_t)b * N_ * N_;

    // stage Q tile (already tf32) into Ps, then pull A-fragments to registers
    {
        const uint4* q4 = (const uint4*)(qb + (size_t)q0 * FO_);
        for (int i = tid; i < BM * (FO_ / 4); i += 256) {
            uint4 v = q4[i];
            uint32_t* d = Ps + (i >> 4) * LS + ((i & 15) << 2);
            d[0] = v.x; d[1] = v.y; d[2] = v.z; d[3] = v.w;
        }
    }
    __syncthreads();
    uint32_t Qa[8][4];
#pragma unroll
    for (int kc = 0; kc < 8; kc++) {
        const uint32_t* Ar = Ps + (rw + gid) * LS + kc * 8 + tig;
        Qa[kc][0] = Ar[0]; Qa[kc][2] = Ar[4];
        Qa[kc][1] = Ar[8 * LS]; Qa[kc][3] = Ar[8 * LS + 4];
    }

    float Oc[8][4];
#pragma unroll
    for (int nt = 0; nt < 8; nt++) { Oc[nt][0] = Oc[nt][1] = Oc[nt][2] = Oc[nt][3] = 0.f; }
    float m0 = 0.f, m1 = 0.f, l0 = 0.f, l1 = 0.f;

    for (int kv0 = 0; kv0 < N_; kv0 += BN) {
        // ---- load K, V (tf32 copy, L2-hot) and x_weight tile (DRAM stream) ----
        {
            const uint4* k4 = (const uint4*)(kb + (size_t)kv0 * FO_);
            const uint4* v4 = (const uint4*)(vb + (size_t)kv0 * FO_);
#pragma unroll
            for (int i = tid; i < BN * (FO_ / 4); i += 256) {
                uint4 kv = k4[i]; uint4 vv = v4[i];
                uint32_t* dk = Ks + (i >> 4) * LS + ((i & 15) << 2);
                uint32_t* dv = Vs + (i >> 4) * LS + ((i & 15) << 2);
                dk[0] = kv.x; dk[1] = kv.y; dk[2] = kv.z; dk[3] = kv.w;
                dv[0] = vv.x; dv[1] = vv.y; dv[2] = vv.z; dv[3] = vv.w;
            }
            const float* wrow = wb + (size_t)q0 * N_ + kv0;
#pragma unroll
            for (int i = tid; i < BM * (BN / 4); i += 256) {
                int r = i >> 4, c4 = (i & 15) << 2;
                float4 wv = *(const float4*)(wrow + (size_t)r * N_ + c4);
                float* d = Wsh + r * LS + c4;
                d[0] = wv.x; d[1] = wv.y; d[2] = wv.z; d[3] = wv.w;
            }
        }
        __syncthreads();

        // ---- S = Q @ K^T ----
        float S[8][4];
#pragma unroll
        for (int nt = 0; nt < 8; nt++) { S[nt][0] = S[nt][1] = S[nt][2] = S[nt][3] = 0.f; }
#pragma unroll
        for (int kc = 0; kc < 8; kc++) {
#pragma unroll
            for (int nt = 0; nt < 8; nt++) {
                // B(k,n) = K[n][k]: Ks stored [kvrow][f]
                const uint32_t* Br = Ks + (nt * 8 + gid) * LS + kc * 8 + tig;
                mma8(S[nt], Qa[kc], Br[0], Br[4]);
            }
        }

        // ---- * x_weight, relu, online softmax ----
        float t0 = m0, t1 = m1;
#pragma unroll
        for (int nt = 0; nt < 8; nt++) {
            const float2 wA = *(const float2*)(Wsh + (rw + gid) * LS + nt * 8 + 2 * tig);
            const float2 wB = *(const float2*)(Wsh + (rw + gid + 8) * LS + nt * 8 + 2 * tig);
            S[nt][0] = fmaxf(S[nt][0] * wA.x, 0.f);
            S[nt][1] = fmaxf(S[nt][1] * wA.y, 0.f);
            S[nt][2] = fmaxf(S[nt][2] * wB.x, 0.f);
            S[nt][3] = fmaxf(S[nt][3] * wB.y, 0.f);
            t0 = fmaxf(t0, fmaxf(S[nt][0], S[nt][1]));
            t1 = fmaxf(t1, fmaxf(S[nt][2], S[nt][3]));
        }
        t0 = fmaxf(t0, __shfl_xor_sync(0xffffffffu, t0, 1));
        t0 = fmaxf(t0, __shfl_xor_sync(0xffffffffu, t0, 2));
        t1 = fmaxf(t1, __shfl_xor_sync(0xffffffffu, t1, 1));
        t1 = fmaxf(t1, __shfl_xor_sync(0xffffffffu, t1, 2));
        const float sc0 = __expf(m0 - t0), sc1 = __expf(m1 - t1);
        m0 = t0; m1 = t1;
        l0 *= sc0; l1 *= sc1;
        float a0 = 0.f, a1 = 0.f;
#pragma unroll
        for (int nt = 0; nt < 8; nt++) {
            Oc[nt][0] *= sc0; Oc[nt][1] *= sc0; Oc[nt][2] *= sc1; Oc[nt][3] *= sc1;
            float p0 = __expf(S[nt][0] - m0), p1 = __expf(S[nt][1] - m0);
            float p2 = __expf(S[nt][2] - m1), p3 = __expf(S[nt][3] - m1);
            a0 += p0 + p1; a1 += p2 + p3;
            uint32_t* d0 = Ps + (rw + gid) * LS + nt * 8 + 2 * tig;
            d0[0] = f2tf(p0); d0[1] = f2tf(p1);
            uint32_t* d1 = Ps + (rw + gid + 8) * LS + nt * 8 + 2 * tig;
            d1[0] = f2tf(p2); d1[1] = f2tf(p3);
        }
        l0 += a0; l1 += a1;
        __syncwarp();   // P tile rows are warp-private

        // ---- O += P @ V ----
#pragma unroll
        for (int kc = 0; kc < 8; kc++) {
            uint32_t a[4];
            const uint32_t* Ar = Ps + (rw + gid) * LS + kc * 8 + tig;
            a[0] = Ar[0]; a[2] = Ar[4]; a[1] = Ar[8 * LS]; a[3] = Ar[8 * LS + 4];
#pragma unroll
            for (int nt = 0; nt < 8; nt++) {
                const uint32_t* Br = Vs + (kc * 8 + tig) * LS + nt * 8 + gid;
                mma8(Oc[nt], a, Br[0], Br[4 * LS]);
            }
        }
        __syncthreads();   // protect Ks/Vs/Wsh before next iteration's loads
    }

    // finalize: reduce l across the quad, normalize, relu, store
    l0 += __shfl_xor_sync(0xffffffffu, l0, 1);
    l0 += __shfl_xor_sync(0xffffffffu, l0, 2);
    l1 += __shfl_xor_sync(0xffffffffu, l1, 1);
    l1 += __shfl_xor_sync(0xffffffffu, l1, 2);
    const float inv0 = 1.f / l0, inv1 = 1.f / l1;
    float* op = out + ((size_t)b * N_ + q0) * FO_;
#pragma unroll
    for (int nt = 0; nt < 8; nt++) {
        int col = nt * 8 + 2 * tig;
        float2 o0 = make_float2(fmaxf(Oc[nt][0] * inv0, 0.f),
                                fmaxf(Oc[nt][1] * inv0, 0.f));
        float2 o1 = make_float2(fmaxf(Oc[nt][2] * inv1, 0.f),
                                fmaxf(Oc[nt][3] * inv1, 0.f));
        *(float2*)(op + (size_t)(rw + gid) * FO_ + col)     = o0;
        *(float2*)(op + (size_t)(rw + gid + 8) * FO_ + col) = o1;
    }
}

// ---------------------------------------------------------------------------
extern "C" void kernel_launch(void* const* d_in, const int* in_sizes, int n_in,
                              void* d_out, int out_size)
{
    const float* feature = (const float*)d_in[0];
    const float* xw      = (const float*)d_in[1];
    const float* W11 = (const float*)d_in[2],  *b11 = (const float*)d_in[3];
    const float* W12 = (const float*)d_in[4],  *b12 = (const float*)d_in[5];
    const float* W21 = (const float*)d_in[6],  *b21 = (const float*)d_in[7];
    const float* W22 = (const float*)d_in[8],  *b22 = (const float*)d_in[9];
    const float* W31 = (const float*)d_in[10], *b31 = (const float*)d_in[11];
    const float* W32 = (const float*)d_in[12], *b32 = (const float*)d_in[13];

    const int mlp_smem  = (64 * LX + 128 * LW + 64 * LW + 64 * LW) * 4;   // 108544
    const int attn_smem = (BN * LS * 2 + BM * LS * 2) * 4;                // 110592
    cudaFuncSetAttribute(mlp_kernel,  cudaFuncAttributeMaxDynamicSharedMemorySize, mlp_smem);
    cudaFuncSetAttribute(attn_kernel, cudaFuncAttributeMaxDynamicSharedMemorySize, attn_smem);

    mlp_kernel<<<dim3((B_ * N_) / 64, 3), 128, mlp_smem>>>(
        feature, W11, b11, W12, b12, W21, b21, W22, b22, W31, b31, W32, b32);

    attn_kernel<<<dim3(N_ / BM, B_), 256, attn_smem>>>(xw, (float*)d_out);
}

// round 4
// speedup vs baseline: 1.3888x; 1.3888x over previous
#include <cuda_runtime.h>
#include <cstdint>

#define B_   2
#define N_   8192
#define FIN_ 128
#define FO_  64

// tf32-pre-rounded q,k,v (bit patterns), 12.6 MB device scratch
__device__ __align__(16) uint32_t g_qkv[3][(size_t)B_ * N_ * FO_];

__device__ __forceinline__ uint32_t f2tf(float x) {
    uint32_t r;
    asm("cvt.rna.tf32.f32 %0, %1;" : "=r"(r) : "f"(x));
    return r;
}

__device__ __forceinline__ void mma8(float c[4], const uint32_t a[4],
                                     uint32_t b0, uint32_t b1) {
    asm volatile(
        "mma.sync.aligned.m16n8k8.row.col.f32.tf32.tf32.f32 "
        "{%0,%1,%2,%3}, {%4,%5,%6,%7}, {%8,%9}, {%0,%1,%2,%3};\n"
        : "+f"(c[0]), "+f"(c[1]), "+f"(c[2]), "+f"(c[3])
        : "r"(a[0]), "r"(a[1]), "r"(a[2]), "r"(a[3]), "r"(b0), "r"(b1));
}

__device__ __forceinline__ void cp16(uint32_t dst, const void* src) {
    asm volatile("cp.async.cg.shared.global [%0], [%1], 16;\n"
                 :: "r"(dst), "l"(src));
}
__device__ __forceinline__ void cp_commit() {
    asm volatile("cp.async.commit_group;\n" ::: "memory");
}
__device__ __forceinline__ void cp_wait1() {
    asm volatile("cp.async.wait_group 1;\n" ::: "memory");
}

// ---------------------------------------------------------------------------
// Kernel 1: fused 2-layer MLP (q/k/v selected by blockIdx.y), 64 rows/block
// ---------------------------------------------------------------------------
#define LX 136   // feature tile row stride (floats)
#define LW 72    // weight / hidden tile row stride (floats)

__global__ void __launch_bounds__(128)
mlp_kernel(const float* __restrict__ feature,
           const float* __restrict__ Wa0, const float* __restrict__ ba0,
           const float* __restrict__ Wb0, const float* __restrict__ bb0,
           const float* __restrict__ Wa1, const float* __restrict__ ba1,
           const float* __restrict__ Wb1, const float* __restrict__ bb1,
           const float* __restrict__ Wa2, const float* __restrict__ ba2,
           const float* __restrict__ Wb2, const float* __restrict__ bb2)
{
    extern __shared__ uint32_t sm_[];
    uint32_t* Xs  = sm_;                  // 64 x LX
    uint32_t* W1s = Xs + 64 * LX;         // 128 x LW
    uint32_t* W2s = W1s + 128 * LW;       // 64 x LW
    uint32_t* Hs  = W2s + 64 * LW;        // 64 x LW

    const int which = blockIdx.y;
    const float* Wa = which == 0 ? Wa0 : which == 1 ? Wa1 : Wa2;
    const float* ba = which == 0 ? ba0 : which == 1 ? ba1 : ba2;
    const float* Wb = which == 0 ? Wb0 : which == 1 ? Wb1 : Wb2;
    const float* bb = which == 0 ? bb0 : which == 1 ? bb1 : bb2;

    const int tid  = threadIdx.x;
    const int row0 = blockIdx.x * 64;

    {
        const float4* f4 = (const float4*)(feature + (size_t)row0 * FIN_);
        for (int i = tid; i < 64 * (FIN_ / 4); i += 128) {
            float4 v = f4[i];
            uint32_t* d = Xs + (i >> 5) * LX + ((i & 31) << 2);
            d[0] = f2tf(v.x); d[1] = f2tf(v.y); d[2] = f2tf(v.z); d[3] = f2tf(v.w);
        }
        const float4* w4 = (const float4*)Wa;     // 128 x 64
        for (int i = tid; i < FIN_ * (FO_ / 4); i += 128) {
            float4 v = w4[i];
            uint32_t* d = W1s + (i >> 4) * LW + ((i & 15) << 2);
            d[0] = f2tf(v.x); d[1] = f2tf(v.y); d[2] = f2tf(v.z); d[3] = f2tf(v.w);
        }
        const float4* w24 = (const float4*)Wb;    // 64 x 64
        for (int i = tid; i < FO_ * (FO_ / 4); i += 128) {
            float4 v = w24[i];
            uint32_t* d = W2s + (i >> 4) * LW + ((i & 15) << 2);
            d[0] = f2tf(v.x); d[1] = f2tf(v.y); d[2] = f2tf(v.z); d[3] = f2tf(v.w);
        }
    }
    __syncthreads();

    const int lane = tid & 31, warp = tid >> 5;
    const int gid = lane >> 2, tig = lane & 3;
    const int rw = warp * 16;

    float C[8][4];
#pragma unroll
    for (int nt = 0; nt < 8; nt++) { C[nt][0] = C[nt][1] = C[nt][2] = C[nt][3] = 0.f; }

    // layer 1: [64x128] @ [128x64]
#pragma unroll
    for (int kc = 0; kc < 16; kc++) {
        uint32_t a[4];
        const uint32_t* Ar = Xs + (rw + gid) * LX + kc * 8 + tig;
        a[0] = Ar[0]; a[2] = Ar[4]; a[1] = Ar[8 * LX]; a[3] = Ar[8 * LX + 4];
#pragma unroll
        for (int nt = 0; nt < 8; nt++) {
            const uint32_t* Br = W1s + (kc * 8 + tig) * LW + nt * 8 + gid;
            mma8(C[nt], a, Br[0], Br[4 * LW]);
        }
    }
#pragma unroll
    for (int nt = 0; nt < 8; nt++) {
        int col = nt * 8 + 2 * tig;
        float bx = ba[col], by = ba[col + 1];
        Hs[(rw + gid) * LW + col]         = f2tf(fmaxf(C[nt][0] + bx, 0.f));
        Hs[(rw + gid) * LW + col + 1]     = f2tf(fmaxf(C[nt][1] + by, 0.f));
        Hs[(rw + gid + 8) * LW + col]     = f2tf(fmaxf(C[nt][2] + bx, 0.f));
        Hs[(rw + gid + 8) * LW + col + 1] = f2tf(fmaxf(C[nt][3] + by, 0.f));
    }
    __syncwarp();

    // layer 2: [64x64] @ [64x64]
#pragma unroll
    for (int nt = 0; nt < 8; nt++) { C[nt][0] = C[nt][1] = C[nt][2] = C[nt][3] = 0.f; }
#pragma unroll
    for (int kc = 0; kc < 8; kc++) {
        uint32_t a[4];
        const uint32_t* Ar = Hs + (rw + gid) * LW + kc * 8 + tig;
        a[0] = Ar[0]; a[2] = Ar[4]; a[1] = Ar[8 * LW]; a[3] = Ar[8 * LW + 4];
#pragma unroll
        for (int nt = 0; nt < 8; nt++) {
            const uint32_t* Br = W2s + (kc * 8 + tig) * LW + nt * 8 + gid;
            mma8(C[nt], a, Br[0], Br[4 * LW]);
        }
    }
    uint32_t* outp = g_qkv[which];
#pragma unroll
    for (int nt = 0; nt < 8; nt++) {
        int col = nt * 8 + 2 * tig;
        float bx = bb[col], by = bb[col + 1];
        uint2 o0 = make_uint2(f2tf(fmaxf(C[nt][0] + bx, 0.f)),
                              f2tf(fmaxf(C[nt][1] + by, 0.f)));
        uint2 o1 = make_uint2(f2tf(fmaxf(C[nt][2] + bx, 0.f)),
                              f2tf(fmaxf(C[nt][3] + by, 0.f)));
        *(uint2*)(outp + (size_t)(row0 + rw + gid) * FO_ + col)     = o0;
        *(uint2*)(outp + (size_t)(row0 + rw + gid + 8) * FO_ + col) = o1;
    }
}

// ---------------------------------------------------------------------------
// Kernel 2: flash attention, double-buffered cp.async pipeline
// BM=128, BN=64, 8 warps
// ---------------------------------------------------------------------------
#define LS 72
#define BM 128
#define BN 64
#define NIT (N_ / BN)

__global__ void __launch_bounds__(256, 1)
attn_kernel(const float* __restrict__ xw, float* __restrict__ out)
{
    extern __shared__ uint32_t sm_[];
    uint32_t* KsB = sm_;                         // 2 x (BN x LS) tf32
    uint32_t* VsB = KsB + 2 * BN * LS;           // 2 x (BN x LS) tf32
    float*    WsB = (float*)(VsB + 2 * BN * LS); // 2 x (BM x LS) fp32
    uint32_t* Ps  = (uint32_t*)WsB + 2 * BM * LS; // BM x LS tf32

    const int b   = blockIdx.y;
    const int q0  = blockIdx.x * BM;
    const int tid = threadIdx.x, lane = tid & 31, warp = tid >> 5;
    const int gid = lane >> 2, tig = lane & 3;
    const int rw  = warp * 16;

    const uint32_t* qb = g_qkv[0] + (size_t)b * N_ * FO_;
    const uint32_t* kb = g_qkv[1] + (size_t)b * N_ * FO_;
    const uint32_t* vb = g_qkv[2] + (size_t)b * N_ * FO_;
    const float*    wb = xw + (size_t)b * N_ * N_;

    // ---- stage Q tile (already tf32) into Ps, pull A-fragments ----
    {
        const uint4* q4 = (const uint4*)(qb + (size_t)q0 * FO_);
        for (int i = tid; i < BM * (FO_ / 4); i += 256) {
            uint4 v = q4[i];
            uint32_t* d = Ps + (i >> 4) * LS + ((i & 15) << 2);
            d[0] = v.x; d[1] = v.y; d[2] = v.z; d[3] = v.w;
        }
    }
    __syncthreads();
    uint32_t Qa[8][4];
#pragma unroll
    for (int kc = 0; kc < 8; kc++) {
        const uint32_t* Ar = Ps + (rw + gid) * LS + kc * 8 + tig;
        Qa[kc][0] = Ar[0]; Qa[kc][2] = Ar[4];
        Qa[kc][1] = Ar[8 * LS]; Qa[kc][3] = Ar[8 * LS + 4];
    }

    // per-thread cp.async slices: K/V 4 chunks each, W 8 chunks
    const int kr  = tid >> 2,            kc4 = (tid & 3) << 2;   // K/V: 4 rows apart
    const int wr  = tid >> 1,            wc4 = (tid & 1) << 3;   // W: 2 chunks/row? no:
    // K/V: chunks i = tid + 256*j, j=0..3 -> row = i>>4, col4 = (i&15)<<2
    // W:   chunks i = tid + 256*j, j=0..7

    auto issue_loads = [&](int it, int buf) {
        const int kv0 = it * BN;
        uint32_t* Kd = KsB + buf * BN * LS;
        uint32_t* Vd = VsB + buf * BN * LS;
        float*    Wd = WsB + buf * BM * LS;
        uint32_t kbase = (uint32_t)__cvta_generic_to_shared(Kd);
        uint32_t vbase = (uint32_t)__cvta_generic_to_shared(Vd);
        uint32_t wbase = (uint32_t)__cvta_generic_to_shared(Wd);
        const uint32_t* ksrc = kb + (size_t)kv0 * FO_;
        const uint32_t* vsrc = vb + (size_t)kv0 * FO_;
        const float*    wsrc = wb + (size_t)q0 * N_ + kv0;
#pragma unroll
        for (int j = 0; j < 4; j++) {
            int i = tid + 256 * j;
            int r = i >> 4, c = (i & 15) << 2;
            uint32_t so = (uint32_t)((r * LS + c) * 4);
            cp16(kbase + so, ksrc + r * FO_ + c);
            cp16(vbase + so, vsrc + r * FO_ + c);
        }
#pragma unroll
        for (int j = 0; j < 8; j++) {
            int i = tid + 256 * j;
            int r = i >> 4, c = (i & 15) << 2;
            cp16(wbase + (uint32_t)((r * LS + c) * 4), wsrc + (size_t)r * N_ + c);
        }
    };

    float Oc[8][4];
#pragma unroll
    for (int nt = 0; nt < 8; nt++) { Oc[nt][0] = Oc[nt][1] = Oc[nt][2] = Oc[nt][3] = 0.f; }
    float m0 = 0.f, m1 = 0.f, l0 = 0.f, l1 = 0.f;

    issue_loads(0, 0);
    cp_commit();

    for (int it = 0; it < NIT; it++) {
        const int buf = it & 1;
        if (it + 1 < NIT) issue_loads(it + 1, buf ^ 1);
        cp_commit();               // empty group on last iter keeps the count
        cp_wait1();                // current tile's group complete
        __syncthreads();

        const uint32_t* Ks = KsB + buf * BN * LS;
        const uint32_t* Vs = VsB + buf * BN * LS;
        const float*    Wsh = WsB + buf * BM * LS;

        // ---- S = Q @ K^T ----
        float S[8][4];
#pragma unroll
        for (int nt = 0; nt < 8; nt++) { S[nt][0] = S[nt][1] = S[nt][2] = S[nt][3] = 0.f; }
#pragma unroll
        for (int kc = 0; kc < 8; kc++) {
#pragma unroll
            for (int nt = 0; nt < 8; nt++) {
                const uint32_t* Br = Ks + (nt * 8 + gid) * LS + kc * 8 + tig;
                mma8(S[nt], Qa[kc], Br[0], Br[4]);
            }
        }

        // ---- * x_weight, relu, online softmax ----
        float t0 = m0, t1 = m1;
#pragma unroll
        for (int nt = 0; nt < 8; nt++) {
            const float2 wA = *(const float2*)(Wsh + (rw + gid) * LS + nt * 8 + 2 * tig);
            const float2 wB = *(const float2*)(Wsh + (rw + gid + 8) * LS + nt * 8 + 2 * tig);
            S[nt][0] = fmaxf(S[nt][0] * wA.x, 0.f);
            S[nt][1] = fmaxf(S[nt][1] * wA.y, 0.f);
            S[nt][2] = fmaxf(S[nt][2] * wB.x, 0.f);
            S[nt][3] = fmaxf(S[nt][3] * wB.y, 0.f);
            t0 = fmaxf(t0, fmaxf(S[nt][0], S[nt][1]));
            t1 = fmaxf(t1, fmaxf(S[nt][2], S[nt][3]));
        }
        t0 = fmaxf(t0, __shfl_xor_sync(0xffffffffu, t0, 1));
        t0 = fmaxf(t0, __shfl_xor_sync(0xffffffffu, t0, 2));
        t1 = fmaxf(t1, __shfl_xor_sync(0xffffffffu, t1, 1));
        t1 = fmaxf(t1, __shfl_xor_sync(0xffffffffu, t1, 2));
        const float sc0 = __expf(m0 - t0), sc1 = __expf(m1 - t1);
        m0 = t0; m1 = t1;
        l0 *= sc0; l1 *= sc1;
        float a0 = 0.f, a1 = 0.f;
#pragma unroll
        for (int nt = 0; nt < 8; nt++) {
            Oc[nt][0] *= sc0; Oc[nt][1] *= sc0; Oc[nt][2] *= sc1; Oc[nt][3] *= sc1;
            float p0 = __expf(S[nt][0] - m0), p1 = __expf(S[nt][1] - m0);
            float p2 = __expf(S[nt][2] - m1), p3 = __expf(S[nt][3] - m1);
            a0 += p0 + p1; a1 += p2 + p3;
            *(uint2*)(Ps + (rw + gid) * LS + nt * 8 + 2 * tig) =
                make_uint2(f2tf(p0), f2tf(p1));
            *(uint2*)(Ps + (rw + gid + 8) * LS + nt * 8 + 2 * tig) =
                make_uint2(f2tf(p2), f2tf(p3));
        }
        l0 += a0; l1 += a1;
        __syncwarp();   // P tile rows are warp-private

        // ---- O += P @ V ----
#pragma unroll
        for (int kc = 0; kc < 8; kc++) {
            uint32_t a[4];
            const uint32_t* Ar = Ps + (rw + gid) * LS + kc * 8 + tig;
            a[0] = Ar[0]; a[2] = Ar[4]; a[1] = Ar[8 * LS]; a[3] = Ar[8 * LS + 4];
#pragma unroll
            for (int nt = 0; nt < 8; nt++) {
                const uint32_t* Br = Vs + (kc * 8 + tig) * LS + nt * 8 + gid;
                mma8(Oc[nt], a, Br[0], Br[4 * LS]);
            }
        }
        __syncthreads();   // everyone done with buf before it+2 overwrites it
    }

    // finalize
    l0 += __shfl_xor_sync(0xffffffffu, l0, 1);
    l0 += __shfl_xor_sync(0xffffffffu, l0, 2);
    l1 += __shfl_xor_sync(0xffffffffu, l1, 1);
    l1 += __shfl_xor_sync(0xffffffffu, l1, 2);
    const float inv0 = 1.f / l0, inv1 = 1.f / l1;
    float* op = out + ((size_t)b * N_ + q0) * FO_;
#pragma unroll
    for (int nt = 0; nt < 8; nt++) {
        int col = nt * 8 + 2 * tig;
        float2 o0 = make_float2(fmaxf(Oc[nt][0] * inv0, 0.f),
                                fmaxf(Oc[nt][1] * inv0, 0.f));
        float2 o1 = make_float2(fmaxf(Oc[nt][2] * inv1, 0.f),
                                fmaxf(Oc[nt][3] * inv1, 0.f));
        *(float2*)(op + (size_t)(rw + gid) * FO_ + col)     = o0;
        *(float2*)(op + (size_t)(rw + gid + 8) * FO_ + col) = o1;
    }
}

// ---------------------------------------------------------------------------
extern "C" void kernel_launch(void* const* d_in, const int* in_sizes, int n_in,
                              void* d_out, int out_size)
{
    const float* feature = (const float*)d_in[0];
    const float* xw      = (const float*)d_in[1];
    const float* W11 = (const float*)d_in[2],  *b11 = (const float*)d_in[3];
    const float* W12 = (const float*)d_in[4],  *b12 = (const float*)d_in[5];
    const float* W21 = (const float*)d_in[6],  *b21 = (const float*)d_in[7];
    const float* W22 = (const float*)d_in[8],  *b22 = (const float*)d_in[9];
    const float* W31 = (const float*)d_in[10], *b31 = (const float*)d_in[11];
    const float* W32 = (const float*)d_in[12], *b32 = (const float*)d_in[13];

    const int mlp_smem  = (64 * LX + 128 * LW + 64 * LW + 64 * LW) * 4;
    const int attn_smem = (2 * BN * LS * 2 + 2 * BM * LS + BM * LS) * 4;   // 184320
    cudaFuncSetAttribute(mlp_kernel,  cudaFuncAttributeMaxDynamicSharedMemorySize, mlp_smem);
    cudaFuncSetAttribute(attn_kernel, cudaFuncAttributeMaxDynamicSharedMemorySize, attn_smem);

    mlp_kernel<<<dim3((B_ * N_) / 64, 3), 128, mlp_smem>>>(
        feature, W11, b11, W12, b12, W21, b21, W22, b22, W31, b31, W32, b32);

    attn_kernel<<<dim3(N_ / BM, B_), 256, attn_smem>>>(xw, (float*)d_out);
}